// round 9
// baseline (speedup 1.0000x reference)
#include <cuda_runtime.h>

// ComposeTransform: out[b] = trilinear(disp1[b], grid + disp2[b]) + disp2[b]
// vol per batch: [D,H,W,3], D=160, H=192, W=160, batch=2.
//
// Two-phase: (1) transpose d1 AoS [v][3] -> SoA scratch [3][v] (dense float
// volumes per channel), (2) gather kernel where each corner load is a 4B
// scalar from a dense volume -> ~half the L1 wavefronts vs AoS gathers.

#define DD 160
#define HH 192
#define WW 160
#define VOX (DD * HH * WW)          // 4,915,200 per batch
#define NTOT (2 * VOX)              // 9,830,400 voxels total
#define NELEM (NTOT * 3)            // 29,491,200 floats

// scratch: channel-split copy of d1 (118 MB), [ch][b*VOX + v]
__device__ float g_soa[(size_t)NELEM];

// ---------------- phase 1: AoS -> SoA transpose (write-coalesced) ----------
__global__ __launch_bounds__(256)
void transpose_kernel(const float* __restrict__ d1)
{
    int t = blockIdx.x * blockDim.x + threadIdx.x;   // 0..NELEM-1
    if (t >= NELEM) return;
    int ch = t / NTOT;              // 0..2 (contiguous output segments)
    int v  = t - ch * NTOT;         // voxel index
    g_soa[t] = __ldg(d1 + (size_t)v * 3 + ch);
}

// ---------------- phase 2: compose with dense per-channel gathers ----------
__global__ __launch_bounds__(256, 8)
void compose_kernel(const float* __restrict__ d2,
                    float* __restrict__ out,
                    int n)
{
    int t = blockIdx.x * blockDim.x + threadIdx.x;
    if (t >= n) return;

    int v  = t / 3;          // voxel index (global, includes batch)
    int ch = t - v * 3;      // channel 0..2

    int b = v / VOX;
    int r = v - b * VOX;
    int x = r / (HH * WW);
    int rem = r - x * (HH * WW);
    int y = rem / WW;
    int z = rem - y * WW;

    // displacement 2 at this voxel (stride-12; warp-local L1 hits)
    const float* pd2 = d2 + (size_t)v * 3;
    float dx = __ldg(pd2 + 0);
    float dy = __ldg(pd2 + 1);
    float dz = __ldg(pd2 + 2);

    float lx = (float)x + dx;
    float ly = (float)y + dy;
    float lz = (float)z + dz;

    float fx = floorf(lx);
    float fy = floorf(ly);
    float fz = floorf(lz);

    // clipped floor / ceil corners (reference semantics)
    float i0x = fminf(fmaxf(fx, 0.0f), (float)(DD - 1));
    float i0y = fminf(fmaxf(fy, 0.0f), (float)(HH - 1));
    float i0z = fminf(fmaxf(fz, 0.0f), (float)(WW - 1));
    float i1x = fminf(fmaxf(fx + 1.0f, 0.0f), (float)(DD - 1));
    float i1y = fminf(fmaxf(fy + 1.0f, 0.0f), (float)(HH - 1));
    float i1z = fminf(fmaxf(fz + 1.0f, 0.0f), (float)(WW - 1));

    // weight attached to floor corner = clip(ceil_clipped - loc, 0, 1)
    float wfx = fminf(fmaxf(i1x - lx, 0.0f), 1.0f);
    float wfy = fminf(fmaxf(i1y - ly, 0.0f), 1.0f);
    float wfz = fminf(fmaxf(i1z - lz, 0.0f), 1.0f);
    float wcx = 1.0f - wfx;
    float wcy = 1.0f - wfy;
    float wcz = 1.0f - wfz;

    int ix0 = (int)i0x, iy0 = (int)i0y, iz0 = (int)i0z;
    int ix1 = (int)i1x, iy1 = (int)i1y, iz1 = (int)i1z;

    // dense per-channel volume base
    const float* vbase = g_soa + (size_t)ch * NTOT + b * VOX;

    int row00 = (ix0 * HH + iy0) * WW;
    int row01 = (ix0 * HH + iy1) * WW;
    int row10 = (ix1 * HH + iy0) * WW;
    int row11 = (ix1 * HH + iy1) * WW;

    float w00z0 = wfx * wfy * wfz;
    float w00z1 = wfx * wfy * wcz;
    float w01z0 = wfx * wcy * wfz;
    float w01z1 = wfx * wcy * wcz;
    float w10z0 = wcx * wfy * wfz;
    float w10z1 = wcx * wfy * wcz;
    float w11z0 = wcx * wcy * wfz;
    float w11z1 = wcx * wcy * wcz;

    // 8 scalar gathers from the dense volume (z-pairs are adjacent floats)
    float g0 = __ldg(vbase + (row00 + iz0));
    float g1 = __ldg(vbase + (row00 + iz1));
    float g2 = __ldg(vbase + (row01 + iz0));
    float g3 = __ldg(vbase + (row01 + iz1));
    float g4 = __ldg(vbase + (row10 + iz0));
    float g5 = __ldg(vbase + (row10 + iz1));
    float g6 = __ldg(vbase + (row11 + iz0));
    float g7 = __ldg(vbase + (row11 + iz1));

    float q0 = fmaf(w00z1, g1, w00z0 * g0);
    float q1 = fmaf(w01z1, g3, w01z0 * g2);
    float q2 = fmaf(w10z1, g5, w10z0 * g4);
    float q3 = fmaf(w11z1, g7, w11z0 * g6);
    float acc = (q0 + q1) + (q2 + q3);

    // add this channel's d2 component
    float d2c = (ch == 0) ? dx : ((ch == 1) ? dy : dz);
    out[t] = acc + d2c;
}

extern "C" void kernel_launch(void* const* d_in, const int* in_sizes, int n_in,
                              void* d_out, int out_size) {
    const float* d1 = (const float*)d_in[0];
    const float* d2 = (const float*)d_in[1];
    float* out = (float*)d_out;
    int n = in_sizes[1];  // 29,491,200 elements

    int threads = 256;
    int blocks = (n + threads - 1) / threads;
    transpose_kernel<<<blocks, threads>>>(d1);
    compose_kernel<<<blocks, threads>>>(d2, out, n);
}

// round 10
// speedup vs baseline: 2.4760x; 2.4760x over previous
#include <cuda_runtime.h>

// ComposeTransform: out[b] = trilinear(disp1[b], grid + disp2[b]) + disp2[b]
// vol per batch: [D,H,W,3], D=160, H=192, W=160, batch=2.
// One thread per (voxel, channel), AoS gathers (triplet lanes share lines),
// block=256 (8 blocks/SM residency), streaming stores, exact grid (no guard).

#define DD 160
#define HH 192
#define WW 160
#define VOX (DD * HH * WW)
#define NELEM (2 * VOX * 3)   // 29,491,200 = 256 * 115,200

__global__ __launch_bounds__(256, 8)
void compose_kernel(const float* __restrict__ d1,
                    const float* __restrict__ d2,
                    float* __restrict__ out)
{
    int t = blockIdx.x * blockDim.x + threadIdx.x;   // exact grid: no guard

    int v  = t / 3;          // voxel index (global, includes batch)
    int ch = t - v * 3;      // channel 0..2

    int b = v / VOX;
    int r = v - b * VOX;
    int x = r / (HH * WW);
    int rem = r - x * (HH * WW);
    int y = rem / WW;
    int z = rem - y * WW;

    // displacement 2 at this voxel (triplet lanes hit the same L1 lines)
    const float* pd2 = d2 + (size_t)v * 3;
    float dx = __ldg(pd2 + 0);
    float dy = __ldg(pd2 + 1);
    float dz = __ldg(pd2 + 2);

    float lx = (float)x + dx;
    float ly = (float)y + dy;
    float lz = (float)z + dz;

    float fx = floorf(lx);
    float fy = floorf(ly);
    float fz = floorf(lz);

    // clipped floor / ceil corners (reference semantics)
    float i0x = fminf(fmaxf(fx, 0.0f), (float)(DD - 1));
    float i0y = fminf(fmaxf(fy, 0.0f), (float)(HH - 1));
    float i0z = fminf(fmaxf(fz, 0.0f), (float)(WW - 1));
    float i1x = fminf(fmaxf(fx + 1.0f, 0.0f), (float)(DD - 1));
    float i1y = fminf(fmaxf(fy + 1.0f, 0.0f), (float)(HH - 1));
    float i1z = fminf(fmaxf(fz + 1.0f, 0.0f), (float)(WW - 1));

    // weight attached to floor corner = clip(ceil_clipped - loc, 0, 1)
    float wfx = fminf(fmaxf(i1x - lx, 0.0f), 1.0f);
    float wfy = fminf(fmaxf(i1y - ly, 0.0f), 1.0f);
    float wfz = fminf(fmaxf(i1z - lz, 0.0f), 1.0f);
    float wcx = 1.0f - wfx;
    float wcy = 1.0f - wfy;
    float wcz = 1.0f - wfz;

    int ix0 = (int)i0x, iy0 = (int)i0y, iz0 = (int)i0z;
    int ix1 = (int)i1x, iy1 = (int)i1y, iz1 = (int)i1z;

    const float* vbase = d1 + (size_t)b * (size_t)(VOX * 3) + ch;

    int row00 = (ix0 * HH + iy0) * (WW * 3);
    int row01 = (ix0 * HH + iy1) * (WW * 3);
    int row10 = (ix1 * HH + iy0) * (WW * 3);
    int row11 = (ix1 * HH + iy1) * (WW * 3);
    int z0 = iz0 * 3;
    int z1 = iz1 * 3;

    float w00z0 = wfx * wfy * wfz;
    float w00z1 = wfx * wfy * wcz;
    float w01z0 = wfx * wcy * wfz;
    float w01z1 = wfx * wcy * wcz;
    float w10z0 = wcx * wfy * wfz;
    float w10z1 = wcx * wfy * wcz;
    float w11z0 = wcx * wcy * wfz;
    float w11z1 = wcx * wcy * wcz;

    // independent loads, tree accumulation
    float g0 = __ldg(vbase + (row00 + z0));
    float g1 = __ldg(vbase + (row00 + z1));
    float g2 = __ldg(vbase + (row01 + z0));
    float g3 = __ldg(vbase + (row01 + z1));
    float g4 = __ldg(vbase + (row10 + z0));
    float g5 = __ldg(vbase + (row10 + z1));
    float g6 = __ldg(vbase + (row11 + z0));
    float g7 = __ldg(vbase + (row11 + z1));

    float q0 = fmaf(w00z1, g1, w00z0 * g0);
    float q1 = fmaf(w01z1, g3, w01z0 * g2);
    float q2 = fmaf(w10z1, g5, w10z0 * g4);
    float q3 = fmaf(w11z1, g7, w11z0 * g6);
    float acc = (q0 + q1) + (q2 + q3);

    // add this channel's d2 component; streaming store (never re-read)
    float d2c = (ch == 0) ? dx : ((ch == 1) ? dy : dz);
    __stcs(out + t, acc + d2c);
}

extern "C" void kernel_launch(void* const* d_in, const int* in_sizes, int n_in,
                              void* d_out, int out_size) {
    const float* d1 = (const float*)d_in[0];
    const float* d2 = (const float*)d_in[1];
    float* out = (float*)d_out;
    // NELEM = 29,491,200 = 256 * 115,200 exactly
    compose_kernel<<<NELEM / 256, 256>>>(d1, d2, out);
}